// round 4
// baseline (speedup 1.0000x reference)
#include <cuda_runtime.h>
#include <stdint.h>

#define VOCAB 50257
#define SEQ   512
#define BATCH 8
#define KD    4      // NUM_DRAFTS
#define LD    8      // DRAFT_LEN
#define NROWS 256    // KD*LD*BATCH
#define LOGITS_ELEMS (BATCH * SEQ * VOCAB)
#define GX    4      // v-dimension blocks per row in sampler
#define PREPB 64     // partial blocks per batch row in prep
#define MARGIN 0.25f

// Packed per-row argmax state: (order-mapped float)<<32 | (0xFFFFFFFF - v)
__device__ unsigned long long g_rowpack[NROWS];
__device__ float g_smax[BATCH];
__device__ float g_pmax[BATCH * PREPB];
__device__ float g_psum[BATCH * PREPB];

// ---- JAX partitionable threefry bits for flat index i (< 2^32):
//      (o0, o1) = threefry2x32(key=(0,42), x0=0, x1=i);  bits = o0 ^ o1
__device__ __forceinline__ uint32_t tf_bits(uint32_t i) {
    const uint32_t ks1 = 42u;
    const uint32_t ks2 = 42u ^ 0x1BD11BDAu;
    uint32_t x0 = 0u;
    uint32_t x1 = i + ks1;
#define TF_R(r) { x0 += x1; x1 = __funnelshift_l(x1, x1, (r)); x1 ^= x0; }
    TF_R(13) TF_R(15) TF_R(26) TF_R(6)
    x0 += ks1; x1 += ks2 + 1u;
    TF_R(17) TF_R(29) TF_R(16) TF_R(24)
    x0 += ks2; x1 += 2u;
    TF_R(13) TF_R(15) TF_R(26) TF_R(6)
    x1 += ks1 + 3u;
    TF_R(17) TF_R(29) TF_R(16) TF_R(24)
    x0 += ks1; x1 += ks2 + 4u;
    TF_R(13) TF_R(15) TF_R(26) TF_R(6)
    x0 += ks2; x1 += 5u;
#undef TF_R
    return x0 ^ x1;
}

// Order-preserving float -> uint32 map
__device__ __forceinline__ uint32_t fmap(float v) {
    uint32_t u = __float_as_uint(v);
    return (u & 0x80000000u) ? ~u : (u | 0x80000000u);
}

// -------- Kernel 1: per-block partial max (deterministic) + rowpack reset ------
__global__ void __launch_bounds__(256)
maxk(const float* __restrict__ logits) {
    int bx = blockIdx.x, b = blockIdx.y, t = threadIdx.x;
    const float* row = logits + ((size_t)b * SEQ + (SEQ - 1)) * VOCAB;
    if (bx == 0 && b == 0 && t == 0) {
        // no concurrent readers of g_rowpack until sampler launch
        for (int i = 0; i < NROWS; i++) g_rowpack[i] = 0ull;
    }
    __shared__ float red[256];
    float m = -INFINITY;
    for (int v = bx * 256 + t; v < VOCAB; v += PREPB * 256) m = fmaxf(m, row[v]);
    red[t] = m; __syncthreads();
    for (int s = 128; s > 0; s >>= 1) {
        if (t < s) red[t] = fmaxf(red[t], red[t + s]);
        __syncthreads();
    }
    if (t == 0) g_pmax[b * PREPB + bx] = red[0];
}

// -------- Kernel 2: per-block partial exp-sum (deterministic) ------------------
__global__ void __launch_bounds__(256)
sumk(const float* __restrict__ logits) {
    int bx = blockIdx.x, b = blockIdx.y, t = threadIdx.x;
    const float* row = logits + ((size_t)b * SEQ + (SEQ - 1)) * VOCAB;
    __shared__ float red[256];
    // every block redundantly reduces the 64 partial maxima (cheap, deterministic)
    float mx = -INFINITY;
    if (t < PREPB) mx = g_pmax[b * PREPB + t];
    red[t] = mx; __syncthreads();
    for (int s = 128; s > 0; s >>= 1) {
        if (t < s) red[t] = fmaxf(red[t], red[t + s]);
        __syncthreads();
    }
    mx = red[0];
    __syncthreads();
    if (bx == 0 && t == 0) g_smax[b] = mx;

    float acc = 0.0f;
    for (int v = bx * 256 + t; v < VOCAB; v += PREPB * 256) acc += expf(row[v] - mx);
    red[t] = acc; __syncthreads();
    for (int s = 128; s > 0; s >>= 1) {
        if (t < s) red[t] += red[t + s];
        __syncthreads();
    }
    if (t == 0) g_psum[b * PREPB + bx] = red[0];
}

// -------- Kernel 3: gumbel-argmax with cheap MUFU screen, exact logf on pass ---
__global__ void __launch_bounds__(256)
sample_kernel(const float* __restrict__ logits) {
    int r = blockIdx.y;          // sampling row (k,l,b) flat; b = r & 7
    int b = r & 7;
    const float* __restrict__ row = logits + ((size_t)b * SEQ + (SEQ - 1)) * VOCAB;

    __shared__ unsigned long long sbest;
    if (threadIdx.x == 0) sbest = 0ull;
    __syncthreads();

    const float tiny = 1.17549435e-38f;
    const float nln2 = -0.69314718056f;
    unsigned long long best = 0ull;
    float bestval = -INFINITY;
    uint32_t base = (uint32_t)r * (uint32_t)VOCAB;
    for (int v = blockIdx.x * 256 + threadIdx.x; v < VOCAB; v += GX * 256) {
        uint32_t bits = tf_bits(base + (uint32_t)v);
        float f = __uint_as_float((bits >> 9) | 0x3f800000u) - 1.0f;  // [0,1)
        float u = fmaxf(tiny, f + tiny);          // JAX uniform(tiny, 1)
        float lgt = __ldg(row + v);

        // cheap bound: gub ~= -log(-log u) via 2x MUFU lg2 (+- ~2e-3 given f-cap)
        float l2u, l2a;
        asm("lg2.approx.f32 %0, %1;" : "=f"(l2u) : "f"(u));
        float a = l2u * nln2;                     // ~ -ln u  (>= 0)
        asm("lg2.approx.f32 %0, %1;" : "=f"(l2a) : "f"(a));
        float gub = l2a * nln2;                   // ~ gumbel

        // skip only when provably losing; NaN/inf bounds fall through to exact.
        // f close to 1 forces exact (MUFU abs-error unreliable there).
        bool provably_lose = (gub + lgt + MARGIN < bestval) && (f < 0.99987793f);
        if (!provably_lose) {
            // exact reference formula (bit-matches XLA's __nv_logf path)
            float val = lgt - logf(-logf(u));
            unsigned long long pk =
                ((unsigned long long)fmap(val) << 32) |
                (unsigned long long)(0xFFFFFFFFu - (uint32_t)v);
            if (pk > best) { best = pk; bestval = val; }
        }
    }
    atomicMax(&sbest, best);
    __syncthreads();
    if (threadIdx.x == 0) atomicMax(&g_rowpack[r], sbest);
}

// -------- Kernel 4: epilogue, reduces partial sums + writes 808 floats ---------
__global__ void __launch_bounds__(NROWS)
finalize_kernel(const float* __restrict__ logits, float* __restrict__ out) {
    __shared__ float probs_s[NROWS];
    __shared__ float meanp_s[BATCH * KD];
    __shared__ float ssum_s[BATCH];
    int o = threadIdx.x;                 // output layout (b, k, l)
    int b = o >> 5, k = (o >> 3) & 3, l = o & 7;
    int rowidx = k * 64 + l * 8 + b;     // gumbel-field row (k, l, b)

    if (o < BATCH) {                     // deterministic fixed-order reduction
        float s = 0.0f;
        #pragma unroll 8
        for (int i = 0; i < PREPB; i++) s += g_psum[o * PREPB + i];
        ssum_s[o] = s;
    }
    __syncthreads();

    unsigned long long pk = g_rowpack[rowidx];
    uint32_t tok = 0xFFFFFFFFu - (uint32_t)(pk & 0xFFFFFFFFull);
    float lg = logits[((size_t)b * SEQ + (SEQ - 1)) * VOCAB + tok];
    float prob = expf(lg - g_smax[b]) / ssum_s[b];

    out[o] = (float)tok;                               // draft_tokens
    out[NROWS + o] = prob;                             // draft_probs
    out[2 * NROWS + o] = (prob >= 0.8f) ? 1.0f : 0.0f; // accepted_mask
    probs_s[o] = prob;
    __syncthreads();

    if (o < BATCH * KD) {                              // (b, k)
        int bb = o >> 2, kk = o & 3;
        float sp = 0.0f, sm = 0.0f;
        #pragma unroll
        for (int ll = 0; ll < LD; ll++) {
            float p = probs_s[bb * 32 + kk * 8 + ll];
            sp += p;
            sm += (p >= 0.8f) ? 1.0f : 0.0f;
        }
        out[3 * NROWS + o] = sm / 8.0f;                // acceptance_ratio
        meanp_s[o] = sp / 8.0f;
    }
    __syncthreads();

    if (o < BATCH) {                                   // best_draft_idx (first max)
        int best = 0;
        float bv = meanp_s[o * 4];
        #pragma unroll
        for (int kk = 1; kk < KD; kk++) {
            float v2 = meanp_s[o * 4 + kk];
            if (v2 > bv) { bv = v2; best = kk; }
        }
        out[3 * NROWS + 32 + o] = (float)best;
    }
}

extern "C" void kernel_launch(void* const* d_in, const int* in_sizes, int n_in,
                              void* d_out, int out_size) {
    int li = 1;
    for (int i = 0; i < n_in; i++) {
        if (in_sizes[i] == LOGITS_ELEMS) { li = i; break; }
    }
    const float* logits = (const float*)d_in[li];
    float* out = (float*)d_out;

    dim3 gprep(PREPB, BATCH);
    maxk<<<gprep, 256>>>(logits);
    sumk<<<gprep, 256>>>(logits);
    dim3 gridB(GX, NROWS);
    sample_kernel<<<gridB, 256>>>(logits);
    finalize_kernel<<<1, NROWS>>>(logits, out);
}

// round 5
// speedup vs baseline: 1.3827x; 1.3827x over previous
#include <cuda_runtime.h>
#include <stdint.h>

#define VOCAB 50257
#define SEQ   512
#define BATCH 8
#define KD    4      // NUM_DRAFTS
#define LD    8      // DRAFT_LEN
#define NROWS 256    // KD*LD*BATCH
#define LOGITS_ELEMS (BATCH * SEQ * VOCAB)
#define GX    4      // v-dimension blocks per row in sampler
#define PREPB 64     // partial blocks per batch row in prep

// Packed per-row argmax state: (order-mapped float)<<32 | (0xFFFFFFFF - v)
__device__ unsigned long long g_rowpack[NROWS];
__device__ float g_smax[BATCH];
__device__ float g_pmax[BATCH * PREPB];
__device__ float g_psum[BATCH * PREPB];

// ---- JAX partitionable threefry bits for flat index i (< 2^32):
//      (o0, o1) = threefry2x32(key=(0,42), x0=0, x1=i);  bits = o0 ^ o1
__device__ __forceinline__ uint32_t tf_bits(uint32_t i) {
    const uint32_t ks1 = 42u;
    const uint32_t ks2 = 42u ^ 0x1BD11BDAu;
    uint32_t x0 = 0u;
    uint32_t x1 = i + ks1;
#define TF_R(r) { x0 += x1; x1 = __funnelshift_l(x1, x1, (r)); x1 ^= x0; }
    TF_R(13) TF_R(15) TF_R(26) TF_R(6)
    x0 += ks1; x1 += ks2 + 1u;
    TF_R(17) TF_R(29) TF_R(16) TF_R(24)
    x0 += ks2; x1 += 2u;
    TF_R(13) TF_R(15) TF_R(26) TF_R(6)
    x1 += ks1 + 3u;
    TF_R(17) TF_R(29) TF_R(16) TF_R(24)
    x0 += ks1; x1 += ks2 + 4u;
    TF_R(13) TF_R(15) TF_R(26) TF_R(6)
    x0 += ks2; x1 += 5u;
#undef TF_R
    return x0 ^ x1;
}

// Order-preserving float -> uint32 map (total order matching IEEE < on reals)
__device__ __forceinline__ uint32_t fmap(float v) {
    uint32_t u = __float_as_uint(v);
    return (u & 0x80000000u) ? ~u : (u | 0x80000000u);
}

// -------- Kernel 1: per-block partial max (deterministic) + rowpack reset ------
__global__ void __launch_bounds__(256)
maxk(const float* __restrict__ logits) {
    int bx = blockIdx.x, b = blockIdx.y, t = threadIdx.x;
    const float* row = logits + ((size_t)b * SEQ + (SEQ - 1)) * VOCAB;
    if (bx == 0 && b == 0 && t == 0) {
        for (int i = 0; i < NROWS; i++) g_rowpack[i] = 0ull;
    }
    __shared__ float red[256];
    float m = -INFINITY;
    for (int v = bx * 256 + t; v < VOCAB; v += PREPB * 256) m = fmaxf(m, row[v]);
    red[t] = m; __syncthreads();
    for (int s = 128; s > 0; s >>= 1) {
        if (t < s) red[t] = fmaxf(red[t], red[t + s]);
        __syncthreads();
    }
    if (t == 0) g_pmax[b * PREPB + bx] = red[0];
}

// -------- Kernel 2: per-block partial exp-sum (deterministic) ------------------
__global__ void __launch_bounds__(256)
sumk(const float* __restrict__ logits) {
    int bx = blockIdx.x, b = blockIdx.y, t = threadIdx.x;
    const float* row = logits + ((size_t)b * SEQ + (SEQ - 1)) * VOCAB;
    __shared__ float red[256];
    float mx = (t < PREPB) ? g_pmax[b * PREPB + t] : -INFINITY;
    red[t] = mx; __syncthreads();
    for (int s = 128; s > 0; s >>= 1) {
        if (t < s) red[t] = fmaxf(red[t], red[t + s]);
        __syncthreads();
    }
    mx = red[0];
    __syncthreads();
    if (bx == 0 && t == 0) g_smax[b] = mx;

    float acc = 0.0f;
    for (int v = bx * 256 + t; v < VOCAB; v += PREPB * 256) acc += expf(row[v] - mx);
    red[t] = acc; __syncthreads();
    for (int s = 128; s > 0; s >>= 1) {
        if (t < s) red[t] += red[t + s];
        __syncthreads();
    }
    if (t == 0) g_psum[b * PREPB + bx] = red[0];
}

// -------- Kernel 3: gumbel-argmax; integer screen + shared rising threshold ----
__global__ void __launch_bounds__(256)
sample_kernel(const float* __restrict__ logits) {
    int r = blockIdx.y;          // sampling row (k,l,b) flat; b = r & 7
    int b = r & 7;
    const float* __restrict__ row = logits + ((size_t)b * SEQ + (SEQ - 1)) * VOCAB;

    __shared__ unsigned long long sbest;
    __shared__ unsigned int s_thr;       // fmap of best exact val achieved in block
    if (threadIdx.x == 0) { sbest = 0ull; s_thr = 0u; }
    __syncthreads();

    const float tiny = 1.17549435e-38f;
    const float ln2 = 0.69314718056f;
    unsigned long long best = 0ull;
    uint32_t base = (uint32_t)r * (uint32_t)VOCAB;
    for (int v = blockIdx.x * 256 + threadIdx.x; v < VOCAB; v += GX * 256) {
        uint32_t bits = tf_bits(base + (uint32_t)v);
        uint32_t m = bits >> 9;                     // 23-bit mantissa
        float lgt = __ldg(row + v);

        // Integer upper bound on gumbel: g(u) <= -ln(1-f) <= (clz(2^23-m)-8)*ln2.
        // bound >= val (real); +3e-5 covers f32 rounding of both sides.
        float cf = (float)(__clz(0x800000u - m) - 8);
        float bound = fmaf(cf, ln2, lgt) + 3e-5f;
        if (fmap(bound) >= s_thr) {                 // can't prove it loses -> exact
            float f = __uint_as_float(m | 0x3f800000u) - 1.0f;   // [0,1)
            float u = fmaxf(tiny, f + tiny);        // JAX uniform(tiny, 1)
            // exact reference formula (bit-matches XLA's __nv_logf path)
            float val = lgt - logf(-logf(u));
            unsigned long long pk =
                ((unsigned long long)fmap(val) << 32) |
                (unsigned long long)(0xFFFFFFFFu - (uint32_t)v);
            if (pk > best) best = pk;
            atomicMax(&s_thr, fmap(val));
        }
    }
    atomicMax(&sbest, best);
    __syncthreads();
    if (threadIdx.x == 0) atomicMax(&g_rowpack[r], sbest);
}

// -------- Kernel 4: epilogue, reduces partial sums + writes 808 floats ---------
__global__ void __launch_bounds__(NROWS)
finalize_kernel(const float* __restrict__ logits, float* __restrict__ out) {
    __shared__ float probs_s[NROWS];
    __shared__ float meanp_s[BATCH * KD];
    __shared__ float ssum_s[BATCH];
    int o = threadIdx.x;                 // output layout (b, k, l)
    int b = o >> 5, k = (o >> 3) & 3, l = o & 7;
    int rowidx = k * 64 + l * 8 + b;     // gumbel-field row (k, l, b)
    int w = o >> 5, lane = o & 31;

    // warp w reduces the 64 partials of batch row w (fixed order per run)
    {
        float s = g_psum[w * PREPB + lane] + g_psum[w * PREPB + 32 + lane];
        #pragma unroll
        for (int sh = 16; sh > 0; sh >>= 1)
            s += __shfl_down_sync(0xFFFFFFFFu, s, sh);
        if (lane == 0) ssum_s[w] = s;
    }
    __syncthreads();

    unsigned long long pk = g_rowpack[rowidx];
    uint32_t tok = 0xFFFFFFFFu - (uint32_t)(pk & 0xFFFFFFFFull);
    float lg = logits[((size_t)b * SEQ + (SEQ - 1)) * VOCAB + tok];
    float prob = expf(lg - g_smax[b]) / ssum_s[b];

    out[o] = (float)tok;                               // draft_tokens
    out[NROWS + o] = prob;                             // draft_probs
    out[2 * NROWS + o] = (prob >= 0.8f) ? 1.0f : 0.0f; // accepted_mask
    probs_s[o] = prob;
    __syncthreads();

    if (o < BATCH * KD) {                              // (b, k)
        int bb = o >> 2, kk = o & 3;
        float sp = 0.0f, sm = 0.0f;
        #pragma unroll
        for (int ll = 0; ll < LD; ll++) {
            float p = probs_s[bb * 32 + kk * 8 + ll];
            sp += p;
            sm += (p >= 0.8f) ? 1.0f : 0.0f;
        }
        out[3 * NROWS + o] = sm / 8.0f;                // acceptance_ratio
        meanp_s[o] = sp / 8.0f;
    }
    __syncthreads();

    if (o < BATCH) {                                   // best_draft_idx (first max)
        int best = 0;
        float bv = meanp_s[o * 4];
        #pragma unroll
        for (int kk = 1; kk < KD; kk++) {
            float v2 = meanp_s[o * 4 + kk];
            if (v2 > bv) { bv = v2; best = kk; }
        }
        out[3 * NROWS + 32 + o] = (float)best;
    }
}

extern "C" void kernel_launch(void* const* d_in, const int* in_sizes, int n_in,
                              void* d_out, int out_size) {
    int li = 1;
    for (int i = 0; i < n_in; i++) {
        if (in_sizes[i] == LOGITS_ELEMS) { li = i; break; }
    }
    const float* logits = (const float*)d_in[li];
    float* out = (float*)d_out;

    dim3 gprep(PREPB, BATCH);
    maxk<<<gprep, 256>>>(logits);
    sumk<<<gprep, 256>>>(logits);
    dim3 gridB(GX, NROWS);
    sample_kernel<<<gridB, 256>>>(logits);
    finalize_kernel<<<1, NROWS>>>(logits, out);
}